// round 1
// baseline (speedup 1.0000x reference)
#include <cuda_runtime.h>

#define THREADS 256
#define HID 100
#define NC 30
#define SD 10
#define BETA_F 3.0f
#define MAXA_F 5.0f

// packed (replicated) weight layout in dynamic SMEM, in ulonglong units
#define OFF_W1T 0        // [100][10]  W1 transposed  (j-major)
#define OFF_B1  1000     // [100]
#define OFF_W2  1100     // [100][30]  (already j-major)
#define OFF_B2  4100     // [30]
#define OFF_L1T 4130     // [100][10]  L1 transposed
#define OFF_BL1 5130     // [100]
#define OFF_WL2 5230     // [100][60]  WL2 transposed to j-major, inner = n*2+d
#define OFF_BL2 11230    // [60]
#define SMEM_ULL 11290
#define SMEM_BYTES (SMEM_ULL * 8)

__device__ __forceinline__ unsigned long long pk2(float x, float y) {
    unsigned long long r;
    asm("mov.b64 %0, {%1, %2};" : "=l"(r) : "f"(x), "f"(y));
    return r;
}

__device__ __forceinline__ float2 unpk(unsigned long long v) {
    float2 r;
    asm("mov.b64 {%0, %1}, %2;" : "=f"(r.x), "=f"(r.y) : "l"(v));
    return r;
}

// packed f32x2 fused multiply-add: d = a*b + c (per 32-bit lane)
__device__ __forceinline__ unsigned long long ffma2(unsigned long long a,
                                                    unsigned long long b,
                                                    unsigned long long c) {
    unsigned long long d;
    asm("fma.rn.f32x2 %0, %1, %2, %3;" : "=l"(d) : "l"(a), "l"(b), "l"(c));
    return d;
}

__device__ __forceinline__ unsigned long long add2(unsigned long long a,
                                                   unsigned long long b) {
    unsigned long long d;
    asm("add.rn.f32x2 %0, %1, %2;" : "=l"(d) : "l"(a), "l"(b));
    return d;
}

__device__ __forceinline__ unsigned long long relu2(unsigned long long h) {
    float2 u = unpk(h);
    return pk2(fmaxf(u.x, 0.0f), fmaxf(u.y, 0.0f));
}

// accurate-enough fast tanh: 1 - 2/(e^{2x}+1); handles +-inf of __expf correctly
__device__ __forceinline__ float tanh_fast(float x) {
    float e = __expf(2.0f * x);
    return 1.0f - __fdividef(2.0f, e + 1.0f);
}

extern "C" __global__ void __launch_bounds__(THREADS)
net_kernel(const float* __restrict__ s,  const float* __restrict__ a,
           const float* __restrict__ W1, const float* __restrict__ b1,
           const float* __restrict__ W2, const float* __restrict__ b2,
           const float* __restrict__ L1, const float* __restrict__ bl1,
           const float* __restrict__ WL2, const float* __restrict__ bL2,
           float* __restrict__ out, int B)
{
    extern __shared__ unsigned long long sm[];
    unsigned long long* pW1T = sm + OFF_W1T;
    unsigned long long* pb1  = sm + OFF_B1;
    unsigned long long* pW2  = sm + OFF_W2;
    unsigned long long* pb2  = sm + OFF_B2;
    unsigned long long* pL1T = sm + OFF_L1T;
    unsigned long long* pbl1 = sm + OFF_BL1;
    unsigned long long* pWL2 = sm + OFF_WL2;
    unsigned long long* pbL2 = sm + OFF_BL2;

    const int t = threadIdx.x;

    // ---- stage weights into SMEM, replicated into both f32x2 lanes ----
    for (int idx = t; idx < HID * SD; idx += THREADS) {       // W1T / L1T
        int j = idx / SD, i = idx % SD;
        float w = W1[i * HID + j];
        pW1T[idx] = pk2(w, w);
        float l = L1[i * HID + j];
        pL1T[idx] = pk2(l, l);
    }
    for (int idx = t; idx < HID * NC; idx += THREADS) {       // W2 (j-major already)
        float w = W2[idx];
        pW2[idx] = pk2(w, w);
    }
    for (int idx = t; idx < HID * 2 * NC; idx += THREADS) {   // WL2 -> [j][n*2+d]
        int j = idx / (2 * NC), nd = idx % (2 * NC);
        int n = nd >> 1, d = nd & 1;
        float w = WL2[n * (HID * 2) + j * 2 + d];
        pWL2[idx] = pk2(w, w);
    }
    for (int idx = t; idx < HID; idx += THREADS) {
        float v1 = b1[idx];  pb1[idx]  = pk2(v1, v1);
        float v2 = bl1[idx]; pbl1[idx] = pk2(v2, v2);
    }
    if (t < NC)     { float v = b2[t];  pb2[t]  = pk2(v, v); }
    if (t < 2 * NC) { float v = bL2[t]; pbL2[t] = pk2(v, v); }
    __syncthreads();

    // ---- each thread handles 2 adjacent rows, packed into f32x2 lanes ----
    const int pairIdx = blockIdx.x * THREADS + t;
    const int r0 = pairIdx * 2;
    if (r0 >= B) return;
    const bool two = (r0 + 1 < B);
    const int r1 = two ? r0 + 1 : r0;

    unsigned long long sp[SD];
    {
        const float2* s0p = (const float2*)(s + (size_t)r0 * SD);
        const float2* s1p = (const float2*)(s + (size_t)r1 * SD);
        #pragma unroll
        for (int i = 0; i < SD / 2; i++) {
            float2 u = s0p[i], v = s1p[i];
            sp[2 * i + 0] = pk2(u.x, v.x);
            sp[2 * i + 1] = pk2(u.y, v.y);
        }
    }

    // ---- sweep 1: location branch -> 60 packed centroid accumulators ----
    unsigned long long cent[2 * NC];
    #pragma unroll
    for (int q = 0; q < 2 * NC; q++) cent[q] = pbL2[q];

    #pragma unroll 2
    for (int j = 0; j < HID; j++) {
        unsigned long long h = pbl1[j];
        const ulonglong2* l1 = (const ulonglong2*)(pL1T + j * SD);
        #pragma unroll
        for (int i = 0; i < SD / 2; i++) {
            ulonglong2 w = l1[i];
            h = ffma2(sp[2 * i + 0], w.x, h);
            h = ffma2(sp[2 * i + 1], w.y, h);
        }
        h = relu2(h);
        const ulonglong2* wl = (const ulonglong2*)(pWL2 + j * (2 * NC));
        #pragma unroll
        for (int q = 0; q < NC; q++) {        // NC pairs of 2 accs
            ulonglong2 w = wl[q];
            cent[2 * q + 0] = ffma2(h, w.x, cent[2 * q + 0]);
            cent[2 * q + 1] = ffma2(h, w.y, cent[2 * q + 1]);
        }
    }

    // ---- epilogue A: centroids -> unnormalized softmax weights e[n] ----
    unsigned long long ew[NC];
    {
        float2 av0 = *(const float2*)(a + (size_t)r0 * 2);
        float2 av1 = *(const float2*)(a + (size_t)r1 * 2);
        #pragma unroll
        for (int n = 0; n < NC; n++) {
            float2 cx = unpk(cent[2 * n + 0]);
            float2 cy = unpk(cent[2 * n + 1]);
            float px0 = MAXA_F * tanh_fast(cx.x);
            float px1 = MAXA_F * tanh_fast(cx.y);
            float py0 = MAXA_F * tanh_fast(cy.x);
            float py1 = MAXA_F * tanh_fast(cy.y);
            float dx0 = px0 - av0.x, dy0 = py0 - av0.y;
            float dx1 = px1 - av1.x, dy1 = py1 - av1.y;
            float d0 = sqrtf(fmaf(dx0, dx0, dy0 * dy0));
            float d1 = sqrtf(fmaf(dx1, dx1, dy1 * dy1));
            ew[n] = pk2(__expf(-BETA_F * d0), __expf(-BETA_F * d1));
        }
    }

    // ---- sweep 2: value branch -> 30 packed value accumulators ----
    unsigned long long vac[NC];
    #pragma unroll
    for (int k = 0; k < NC; k++) vac[k] = pb2[k];

    #pragma unroll 2
    for (int j = 0; j < HID; j++) {
        unsigned long long h = pb1[j];
        const ulonglong2* w1 = (const ulonglong2*)(pW1T + j * SD);
        #pragma unroll
        for (int i = 0; i < SD / 2; i++) {
            ulonglong2 w = w1[i];
            h = ffma2(sp[2 * i + 0], w.x, h);
            h = ffma2(sp[2 * i + 1], w.y, h);
        }
        h = relu2(h);
        const ulonglong2* w2 = (const ulonglong2*)(pW2 + j * NC);
        #pragma unroll
        for (int k = 0; k < NC / 2; k++) {
            ulonglong2 w = w2[k];
            vac[2 * k + 0] = ffma2(h, w.x, vac[2 * k + 0]);
            vac[2 * k + 1] = ffma2(h, w.y, vac[2 * k + 1]);
        }
    }

    // ---- epilogue B: weighted sum / softmax normalization ----
    unsigned long long num = 0ULL, den = 0ULL;
    #pragma unroll
    for (int n = 0; n < NC; n++) {
        num = ffma2(ew[n], vac[n], num);
        den = add2(den, ew[n]);
    }
    float2 nn = unpk(num);
    float2 dd = unpk(den);
    out[r0] = nn.x / dd.x;
    if (two) out[r0 + 1] = nn.y / dd.y;
}

extern "C" void kernel_launch(void* const* d_in, const int* in_sizes, int n_in,
                              void* d_out, int out_size) {
    const float* s   = (const float*)d_in[0];
    const float* a   = (const float*)d_in[1];
    const float* W1  = (const float*)d_in[2];
    const float* b1  = (const float*)d_in[3];
    const float* W2  = (const float*)d_in[4];
    const float* b2  = (const float*)d_in[5];
    const float* L1  = (const float*)d_in[6];
    const float* bl1 = (const float*)d_in[7];
    const float* WL2 = (const float*)d_in[8];
    const float* bL2 = (const float*)d_in[9];
    float* out = (float*)d_out;

    const int B = in_sizes[0] / SD;
    const int pairs = (B + 1) / 2;
    const int blocks = (pairs + THREADS - 1) / THREADS;

    cudaFuncSetAttribute((const void*)net_kernel,
                         cudaFuncAttributeMaxDynamicSharedMemorySize, SMEM_BYTES);
    net_kernel<<<blocks, THREADS, SMEM_BYTES>>>(s, a, W1, b1, W2, b2,
                                                L1, bl1, WL2, bL2, out, B);
}

// round 2
// speedup vs baseline: 1.1158x; 1.1158x over previous
#include <cuda_runtime.h>

#define THREADS 256
#define HID 100
#define NC 30
#define SD 10
#define BETA_F 3.0f
#define MAXA_F 5.0f

// SMEM layout in ulonglong (f32x2 pair) units; all offsets EVEN so that
// ulonglong2 (LDS.128) accesses stay 16B-aligned.
#define OFF_W1  0        // [50][10]  (W1[i][2m], W1[i][2m+1]) per (m,i)
#define OFF_B1  500      // [50]      (b1[2m], b1[2m+1])
#define OFF_W2  550      // [100][16] (W2[j][2k], W2[j][2k+1]) per (j,k), padded 15->16
#define OFF_B2  2150     // [16]      (b2[2k], b2[2k+1]) (15 used)
#define OFF_L1  2166     // [50][10]
#define OFF_BL1 2666     // [50]
#define OFF_WL2 2716     // [100][30] (WL2[n][j][0], WL2[n][j][1]) per (j,n)
#define OFF_BL2 5716     // [30]      (bL2[n][0], bL2[n][1])
#define SMEM_ULL 5746
#define SMEM_BYTES (SMEM_ULL * 8)

__device__ __forceinline__ unsigned long long pk2(float x, float y) {
    unsigned long long r;
    asm("mov.b64 %0, {%1, %2};" : "=l"(r) : "f"(x), "f"(y));
    return r;
}

__device__ __forceinline__ float2 unpk(unsigned long long v) {
    float2 r;
    asm("mov.b64 {%0, %1}, %2;" : "=f"(r.x), "=f"(r.y) : "l"(v));
    return r;
}

// packed f32x2 fused multiply-add: d = a*b + c (per 32-bit lane)
__device__ __forceinline__ unsigned long long ffma2(unsigned long long a,
                                                    unsigned long long b,
                                                    unsigned long long c) {
    unsigned long long d;
    asm("fma.rn.f32x2 %0, %1, %2, %3;" : "=l"(d) : "l"(a), "l"(b), "l"(c));
    return d;
}

__device__ __forceinline__ unsigned long long relu2(unsigned long long h) {
    float2 u = unpk(h);
    return pk2(fmaxf(u.x, 0.0f), fmaxf(u.y, 0.0f));
}

// accurate fast tanh: 1 - 2/(e^{2x}+1); handles +-inf of __expf correctly
__device__ __forceinline__ float tanh_fast(float x) {
    float e = __expf(2.0f * x);
    return 1.0f - __fdividef(2.0f, e + 1.0f);
}

extern "C" __global__ void __launch_bounds__(THREADS, 2)
net_kernel(const float* __restrict__ s,  const float* __restrict__ a,
           const float* __restrict__ W1, const float* __restrict__ b1,
           const float* __restrict__ W2, const float* __restrict__ b2,
           const float* __restrict__ L1, const float* __restrict__ bl1,
           const float* __restrict__ WL2, const float* __restrict__ bL2,
           float* __restrict__ out, int B)
{
    extern __shared__ unsigned long long sm[];
    const int t = threadIdx.x;

    // ---- stage weights into SMEM as adjacent-output f32x2 pairs ----
    for (int idx = t; idx < 500; idx += THREADS) {           // W1 / L1 interleaved
        int m = idx / SD, i = idx % SD;
        sm[OFF_W1 + idx] = pk2(W1[i * HID + 2 * m], W1[i * HID + 2 * m + 1]);
        sm[OFF_L1 + idx] = pk2(L1[i * HID + 2 * m], L1[i * HID + 2 * m + 1]);
    }
    for (int idx = t; idx < HID * 16; idx += THREADS) {      // W2 padded pairs
        int j = idx / 16, k = idx % 16;
        unsigned long long v = 0ULL;
        if (k < 15) v = pk2(W2[j * NC + 2 * k], W2[j * NC + 2 * k + 1]);
        sm[OFF_W2 + idx] = v;
    }
    for (int idx = t; idx < HID * NC; idx += THREADS) {      // WL2 -> [j][n] (x,y)
        int j = idx / NC, n = idx % NC;
        sm[OFF_WL2 + idx] = pk2(WL2[n * (HID * 2) + j * 2 + 0],
                                WL2[n * (HID * 2) + j * 2 + 1]);
    }
    for (int idx = t; idx < 50; idx += THREADS) {
        sm[OFF_B1  + idx] = pk2(b1 [2 * idx], b1 [2 * idx + 1]);
        sm[OFF_BL1 + idx] = pk2(bl1[2 * idx], bl1[2 * idx + 1]);
    }
    if (t < 15) sm[OFF_B2  + t] = pk2(b2 [2 * t], b2 [2 * t + 1]);
    if (t < NC) sm[OFF_BL2 + t] = pk2(bL2[2 * t], bL2[2 * t + 1]);
    __syncthreads();

    const int row = blockIdx.x * THREADS + t;
    if (row >= B) return;

    // ---- load s, pre-broadcast each element into both f32x2 lanes ----
    unsigned long long sb[SD];
    {
        const float2* sp = (const float2*)(s + (size_t)row * SD);
        #pragma unroll
        for (int i = 0; i < SD / 2; i++) {
            float2 u = sp[i];
            sb[2 * i + 0] = pk2(u.x, u.x);
            sb[2 * i + 1] = pk2(u.y, u.y);
        }
    }
    const float2 av = *(const float2*)(a + (size_t)row * 2);

    // ================= sweep 1: location branch =================
    // cent[n] packs (centroid_x, centroid_y) for centroid n
    unsigned long long cent[NC];
    #pragma unroll
    for (int n = 0; n < NC; n++) cent[n] = sm[OFF_BL2 + n];

    {
        const unsigned long long* w1row = sm + OFF_L1;
        const unsigned long long* bprow = sm + OFF_BL1;
        const unsigned long long* w2row = sm + OFF_WL2;
        #pragma unroll 2
        for (int m = 0; m < 50; m++) {
            unsigned long long hp = bprow[m];
            const ulonglong2* wr = (const ulonglong2*)(w1row + m * SD);
            #pragma unroll
            for (int i = 0; i < SD / 2; i++) {
                ulonglong2 w = wr[i];
                hp = ffma2(sb[2 * i + 0], w.x, hp);
                hp = ffma2(sb[2 * i + 1], w.y, hp);
            }
            hp = relu2(hp);
            float2 hu = unpk(hp);
            unsigned long long h0 = pk2(hu.x, hu.x);
            unsigned long long h1 = pk2(hu.y, hu.y);
            const ulonglong2* wa = (const ulonglong2*)(w2row + (2 * m + 0) * NC);
            const ulonglong2* wb = (const ulonglong2*)(w2row + (2 * m + 1) * NC);
            #pragma unroll
            for (int q = 0; q < NC / 2; q++) {
                ulonglong2 ua = wa[q];
                cent[2 * q + 0] = ffma2(h0, ua.x, cent[2 * q + 0]);
                cent[2 * q + 1] = ffma2(h0, ua.y, cent[2 * q + 1]);
                ulonglong2 ub = wb[q];
                cent[2 * q + 0] = ffma2(h1, ub.x, cent[2 * q + 0]);
                cent[2 * q + 1] = ffma2(h1, ub.y, cent[2 * q + 1]);
            }
        }
    }

    // ---- epilogue A: centroids -> unnormalized softmax weights ----
    float ew[NC];
    #pragma unroll
    for (int n = 0; n < NC; n++) {
        float2 c = unpk(cent[n]);
        float px = MAXA_F * tanh_fast(c.x);
        float py = MAXA_F * tanh_fast(c.y);
        float dx = px - av.x, dy = py - av.y;
        float d = sqrtf(fmaf(dx, dx, dy * dy));
        ew[n] = __expf(-BETA_F * d);
    }

    // ================= sweep 2: value branch =================
    unsigned long long vac[15];
    #pragma unroll
    for (int k = 0; k < 15; k++) vac[k] = sm[OFF_B2 + k];

    {
        const unsigned long long* w1row = sm + OFF_W1;
        const unsigned long long* bprow = sm + OFF_B1;
        const unsigned long long* w2row = sm + OFF_W2;
        #pragma unroll 2
        for (int m = 0; m < 50; m++) {
            unsigned long long hp = bprow[m];
            const ulonglong2* wr = (const ulonglong2*)(w1row + m * SD);
            #pragma unroll
            for (int i = 0; i < SD / 2; i++) {
                ulonglong2 w = wr[i];
                hp = ffma2(sb[2 * i + 0], w.x, hp);
                hp = ffma2(sb[2 * i + 1], w.y, hp);
            }
            hp = relu2(hp);
            float2 hu = unpk(hp);
            unsigned long long h0 = pk2(hu.x, hu.x);
            unsigned long long h1 = pk2(hu.y, hu.y);
            const ulonglong2* wa = (const ulonglong2*)(w2row + (2 * m + 0) * 16);
            const ulonglong2* wb = (const ulonglong2*)(w2row + (2 * m + 1) * 16);
            #pragma unroll
            for (int q = 0; q < 7; q++) {
                ulonglong2 ua = wa[q];
                vac[2 * q + 0] = ffma2(h0, ua.x, vac[2 * q + 0]);
                vac[2 * q + 1] = ffma2(h0, ua.y, vac[2 * q + 1]);
                ulonglong2 ub = wb[q];
                vac[2 * q + 0] = ffma2(h1, ub.x, vac[2 * q + 0]);
                vac[2 * q + 1] = ffma2(h1, ub.y, vac[2 * q + 1]);
            }
            // tail pair k=14
            vac[14] = ffma2(h0, w2row[(2 * m + 0) * 16 + 14], vac[14]);
            vac[14] = ffma2(h1, w2row[(2 * m + 1) * 16 + 14], vac[14]);
        }
    }

    // ---- epilogue B: softmax-weighted sum ----
    float num = 0.0f, den = 0.0f;
    #pragma unroll
    for (int k = 0; k < 15; k++) {
        float2 vv = unpk(vac[k]);
        num = fmaf(ew[2 * k], vv.x, num);
        num = fmaf(ew[2 * k + 1], vv.y, num);
        den += ew[2 * k] + ew[2 * k + 1];
    }
    out[row] = num / den;
}

extern "C" void kernel_launch(void* const* d_in, const int* in_sizes, int n_in,
                              void* d_out, int out_size) {
    const float* s   = (const float*)d_in[0];
    const float* a   = (const float*)d_in[1];
    const float* W1  = (const float*)d_in[2];
    const float* b1  = (const float*)d_in[3];
    const float* W2  = (const float*)d_in[4];
    const float* b2  = (const float*)d_in[5];
    const float* L1  = (const float*)d_in[6];
    const float* bl1 = (const float*)d_in[7];
    const float* WL2 = (const float*)d_in[8];
    const float* bL2 = (const float*)d_in[9];
    float* out = (float*)d_out;

    const int B = in_sizes[0] / SD;
    const int blocks = (B + THREADS - 1) / THREADS;

    cudaFuncSetAttribute((const void*)net_kernel,
                         cudaFuncAttributeMaxDynamicSharedMemorySize, SMEM_BYTES);
    net_kernel<<<blocks, THREADS, SMEM_BYTES>>>(s, a, W1, b1, W2, b2,
                                                L1, bl1, WL2, bL2, out, B);
}

// round 3
// speedup vs baseline: 1.2270x; 1.0996x over previous
#include <cuda_runtime.h>

#define THREADS 256
#define HID 100
#define NC 30
#define SD 10
#define BETA_F 3.0f
#define MAXA_F 5.0f

typedef unsigned long long ull;

// ---- SMEM layout (ull units); all bases even -> 16B aligned ----
#define OFF_L1R  0      // [100][10] replicated (w,w)
#define OFF_BL1R 1000   // [100]     replicated (b,b)
#define OFF_W1R  1100   // [100][10] replicated
#define OFF_B1R  2100   // [100]
#define OFF_WL2A 2200   // [100][16] pairs (x,y), centroids 0..15
#define OFF_WL2B 3800   // [100][14] centroids 16..29
#define OFF_W2A  5200   // [100][8]  value pairs k=0..7
#define OFF_W2B  6000   // [100][8]  value pairs k=8..14 (slot 7 zero)
#define OFF_BL2A 6800   // [16]
#define OFF_BL2B 6816   // [14] (16 reserved)
#define OFF_B2A  6832   // [8]
#define OFF_B2B  6840   // [8] (7 used)
#define SMEM_ULL 6848
#define SMEM_BYTES (SMEM_ULL * 8)

__device__ __forceinline__ ull pk2(float x, float y) {
    ull r; asm("mov.b64 %0, {%1, %2};" : "=l"(r) : "f"(x), "f"(y)); return r;
}
__device__ __forceinline__ float2 unpk(ull v) {
    float2 r; asm("mov.b64 {%0, %1}, %2;" : "=f"(r.x), "=f"(r.y) : "l"(v)); return r;
}
__device__ __forceinline__ ull ffma2(ull a, ull b, ull c) {
    ull d; asm("fma.rn.f32x2 %0, %1, %2, %3;" : "=l"(d) : "l"(a), "l"(b), "l"(c)); return d;
}
__device__ __forceinline__ ull add2(ull a, ull b) {
    ull d; asm("add.rn.f32x2 %0, %1, %2;" : "=l"(d) : "l"(a), "l"(b)); return d;
}
__device__ __forceinline__ ull relu2(ull h) {
    float2 u = unpk(h);
    return pk2(fmaxf(u.x, 0.0f), fmaxf(u.y, 0.0f));
}
// accurate fast tanh: 1 - 2/(e^{2x}+1); correct at +-inf of __expf
__device__ __forceinline__ float tanh_fast(float x) {
    float e = __expf(2.0f * x);
    return 1.0f - __fdividef(2.0f, e + 1.0f);
}

// One fused pass: layer1 (row-packed, replicated weights) + layer2 with NP
// pair-packed weight columns per hidden unit. acc_r0/acc_r1: NP ull each.
// ST = row stride of w2 in ull.
template<int NP, int ST>
__device__ __forceinline__ void layer_pass(
    const ull* __restrict__ w1, const ull* __restrict__ b1p,
    const ull* __restrict__ w2, const ull* __restrict__ binit,
    const ull* __restrict__ sb, ull* acc_r0, ull* acc_r1)
{
    #pragma unroll
    for (int q = 0; q < NP; q++) { acc_r0[q] = binit[q]; acc_r1[q] = binit[q]; }
    #pragma unroll 2
    for (int j = 0; j < HID; j++) {
        ull h = b1p[j];
        const ulonglong2* wr = (const ulonglong2*)(w1 + j * SD);
        #pragma unroll
        for (int i = 0; i < SD / 2; i++) {
            ulonglong2 w = wr[i];
            h = ffma2(sb[2 * i + 0], w.x, h);
            h = ffma2(sb[2 * i + 1], w.y, h);
        }
        h = relu2(h);
        float2 hu = unpk(h);
        ull h0 = pk2(hu.x, hu.x);          // row0 h, splat
        ull h1 = pk2(hu.y, hu.y);          // row1 h, splat
        const ull* w2j = w2 + j * ST;
        #pragma unroll
        for (int q = 0; q < NP / 2; q++) {
            ulonglong2 w = ((const ulonglong2*)w2j)[q];
            acc_r0[2 * q + 0] = ffma2(h0, w.x, acc_r0[2 * q + 0]);
            acc_r0[2 * q + 1] = ffma2(h0, w.y, acc_r0[2 * q + 1]);
            acc_r1[2 * q + 0] = ffma2(h1, w.x, acc_r1[2 * q + 0]);
            acc_r1[2 * q + 1] = ffma2(h1, w.y, acc_r1[2 * q + 1]);
        }
        if (NP & 1) {
            ull w = w2j[NP - 1];
            acc_r0[NP - 1] = ffma2(h0, w, acc_r0[NP - 1]);
            acc_r1[NP - 1] = ffma2(h1, w, acc_r1[NP - 1]);
        }
    }
}

// centroid accs -> row-packed unnormalized softmax weights ewp[M]
template<int M>
__device__ __forceinline__ void centroids_to_ew(
    const ull* cr0, const ull* cr1, float2 av0, float2 av1, ull* ewp)
{
    #pragma unroll
    for (int n = 0; n < M; n++) {
        float2 c0 = unpk(cr0[n]);
        float2 c1 = unpk(cr1[n]);
        float px0 = MAXA_F * tanh_fast(c0.x), py0 = MAXA_F * tanh_fast(c0.y);
        float px1 = MAXA_F * tanh_fast(c1.x), py1 = MAXA_F * tanh_fast(c1.y);
        float dx0 = px0 - av0.x, dy0 = py0 - av0.y;
        float dx1 = px1 - av1.x, dy1 = py1 - av1.y;
        float d0 = sqrtf(fmaf(dx0, dx0, dy0 * dy0));
        float d1 = sqrtf(fmaf(dx1, dx1, dy1 * dy1));
        ewp[n] = pk2(__expf(-BETA_F * d0), __expf(-BETA_F * d1));
    }
}

// fold KP value pairs with 2*KP row-packed ew into num/den (row-packed)
template<int KP>
__device__ __forceinline__ void fold(
    const ull* vr0, const ull* vr1, const ull* ewp, ull& num, ull& den)
{
    #pragma unroll
    for (int k = 0; k < KP; k++) {
        float2 v0 = unpk(vr0[k]);          // (v_{2k}, v_{2k+1}) row0
        float2 v1 = unpk(vr1[k]);          // row1
        num = ffma2(ewp[2 * k + 0], pk2(v0.x, v1.x), num);
        num = ffma2(ewp[2 * k + 1], pk2(v0.y, v1.y), num);
        den = add2(den, add2(ewp[2 * k], ewp[2 * k + 1]));
    }
}

extern "C" __global__ void __launch_bounds__(THREADS, 2)
net_kernel(const float* __restrict__ s,  const float* __restrict__ a,
           const float* __restrict__ W1, const float* __restrict__ b1,
           const float* __restrict__ W2, const float* __restrict__ b2,
           const float* __restrict__ L1, const float* __restrict__ bl1,
           const float* __restrict__ WL2, const float* __restrict__ bL2,
           float* __restrict__ out, int B)
{
    extern __shared__ ull sm[];
    const int t = threadIdx.x;

    // ---- stage weights ----
    for (int idx = t; idx < HID * SD; idx += THREADS) {   // replicated layer1
        int j = idx / SD, i = idx % SD;
        float w = L1[i * HID + j]; sm[OFF_L1R + idx] = pk2(w, w);
        float v = W1[i * HID + j]; sm[OFF_W1R + idx] = pk2(v, v);
    }
    for (int idx = t; idx < HID; idx += THREADS) {
        float v1 = bl1[idx]; sm[OFF_BL1R + idx] = pk2(v1, v1);
        float v2 = b1[idx];  sm[OFF_B1R  + idx] = pk2(v2, v2);
    }
    for (int idx = t; idx < HID * 16; idx += THREADS) {   // WL2A: centroids 0..15
        int j = idx / 16, n = idx % 16;
        sm[OFF_WL2A + idx] = pk2(WL2[n * (HID * 2) + 2 * j], WL2[n * (HID * 2) + 2 * j + 1]);
    }
    for (int idx = t; idx < HID * 14; idx += THREADS) {   // WL2B: centroids 16..29
        int j = idx / 14, n = 16 + idx % 14;
        sm[OFF_WL2B + idx] = pk2(WL2[n * (HID * 2) + 2 * j], WL2[n * (HID * 2) + 2 * j + 1]);
    }
    for (int idx = t; idx < HID * 8; idx += THREADS) {    // W2A: pairs k=0..7
        int j = idx / 8, k = idx % 8;
        sm[OFF_W2A + idx] = pk2(W2[j * NC + 2 * k], W2[j * NC + 2 * k + 1]);
        int kb = 8 + k;                                    // W2B: pairs k=8..14
        sm[OFF_W2B + idx] = (kb < 15)
            ? pk2(W2[j * NC + 2 * kb], W2[j * NC + 2 * kb + 1]) : 0ULL;
    }
    if (t < 16) sm[OFF_BL2A + t] = pk2(bL2[2 * t], bL2[2 * t + 1]);
    if (t < 14) { int n = 16 + t; sm[OFF_BL2B + t] = pk2(bL2[2 * n], bL2[2 * n + 1]); }
    if (t < 8) {
        sm[OFF_B2A + t] = pk2(b2[2 * t], b2[2 * t + 1]);
        int kb = 8 + t;
        sm[OFF_B2B + t] = (kb < 15) ? pk2(b2[2 * kb], b2[2 * kb + 1]) : 0ULL;
    }
    __syncthreads();

    const int pairIdx = blockIdx.x * THREADS + t;
    const int r0 = 2 * pairIdx;
    if (r0 >= B) return;
    const bool two = (r0 + 1 < B);
    const int r1 = two ? r0 + 1 : r0;

    // row-packed s: sb[i] = (s_r0[i], s_r1[i])
    ull sb[SD];
    {
        const float2* s0 = (const float2*)(s + (size_t)r0 * SD);
        const float2* s1 = (const float2*)(s + (size_t)r1 * SD);
        #pragma unroll
        for (int i = 0; i < SD / 2; i++) {
            float2 u = s0[i], v = s1[i];
            sb[2 * i + 0] = pk2(u.x, v.x);
            sb[2 * i + 1] = pk2(u.y, v.y);
        }
    }
    const float2 av0 = *(const float2*)(a + (size_t)r0 * 2);
    const float2 av1 = *(const float2*)(a + (size_t)r1 * 2);

    ull num = 0ULL, den = 0ULL;

    // ===== phase 1: centroids 0..15 =====
    ull ewA[16];
    {
        ull cr0[16], cr1[16];
        layer_pass<16, 16>(sm + OFF_L1R, sm + OFF_BL1R, sm + OFF_WL2A,
                           sm + OFF_BL2A, sb, cr0, cr1);
        centroids_to_ew<16>(cr0, cr1, av0, av1, ewA);
    }
    // ===== phase 2: values 0..15, fold =====
    {
        ull vr0[8], vr1[8];
        layer_pass<8, 8>(sm + OFF_W1R, sm + OFF_B1R, sm + OFF_W2A,
                         sm + OFF_B2A, sb, vr0, vr1);
        fold<8>(vr0, vr1, ewA, num, den);
    }
    // ===== phase 3: centroids 16..29 =====
    ull ewB[14];
    {
        ull cr0[14], cr1[14];
        layer_pass<14, 14>(sm + OFF_L1R, sm + OFF_BL1R, sm + OFF_WL2B,
                           sm + OFF_BL2B, sb, cr0, cr1);
        centroids_to_ew<14>(cr0, cr1, av0, av1, ewB);
    }
    // ===== phase 4: values 16..29, fold =====
    {
        ull vr0[7], vr1[7];
        layer_pass<7, 8>(sm + OFF_W1R, sm + OFF_B1R, sm + OFF_W2B,
                         sm + OFF_B2B, sb, vr0, vr1);
        fold<7>(vr0, vr1, ewB, num, den);
    }

    float2 nn = unpk(num);
    float2 dd = unpk(den);
    out[r0] = nn.x / dd.x;
    if (two) out[r0 + 1] = nn.y / dd.y;
}

extern "C" void kernel_launch(void* const* d_in, const int* in_sizes, int n_in,
                              void* d_out, int out_size) {
    const float* s   = (const float*)d_in[0];
    const float* a   = (const float*)d_in[1];
    const float* W1  = (const float*)d_in[2];
    const float* b1  = (const float*)d_in[3];
    const float* W2  = (const float*)d_in[4];
    const float* b2  = (const float*)d_in[5];
    const float* L1  = (const float*)d_in[6];
    const float* bl1 = (const float*)d_in[7];
    const float* WL2 = (const float*)d_in[8];
    const float* bL2 = (const float*)d_in[9];
    float* out = (float*)d_out;

    const int B = in_sizes[0] / SD;
    const int pairs = (B + 1) / 2;
    const int blocks = (pairs + THREADS - 1) / THREADS;

    cudaFuncSetAttribute((const void*)net_kernel,
                         cudaFuncAttributeMaxDynamicSharedMemorySize, SMEM_BYTES);
    net_kernel<<<blocks, THREADS, SMEM_BYTES>>>(s, a, W1, b1, W2, b2,
                                                L1, bl1, WL2, bL2, out, B);
}

// round 4
// speedup vs baseline: 1.2677x; 1.0332x over previous
#include <cuda_runtime.h>

#define THREADS 256
#define HID 100
#define NC 30
#define SD 10
#define BETA_F 3.0f
#define MAXA_F 5.0f

typedef unsigned long long ull;

// ---- constant bank layout (ull units) ----
#define CW1T 0       // [100][5]  (W1[2p][j], W1[2p+1][j])  K-pair-packed, transposed
#define CL1T 500     // [100][5]
#define CB1  1000    // [100]     (b1[j], 0)
#define CBL1 1100    // [100]     (bl1[j], 0)
#define CONST_ULL 1200
__constant__ ull cb[CONST_ULL];
__device__ ull d_scratch[CONST_ULL];

// ---- SMEM layout (ull units, layer-2 only); bases even -> 16B aligned ----
#define OFF_WL2A 0      // [100][16] pairs (x,y), centroids 0..15
#define OFF_WL2B 1600   // [100][14] centroids 16..29
#define OFF_W2A  3000   // [100][8]  value pairs k=0..7
#define OFF_W2B  3800   // [100][8]  value pairs k=8..14 (slot 7 zero)
#define OFF_BL2A 4600   // [16]
#define OFF_BL2B 4616   // [16] (14 used)
#define OFF_B2A  4632   // [8]
#define OFF_B2B  4640   // [8] (7 used)
#define SMEM_ULL 4648
#define SMEM_BYTES (SMEM_ULL * 8)

__device__ __forceinline__ ull pk2(float x, float y) {
    ull r; asm("mov.b64 %0, {%1, %2};" : "=l"(r) : "f"(x), "f"(y)); return r;
}
__device__ __forceinline__ float2 unpk(ull v) {
    float2 r; asm("mov.b64 {%0, %1}, %2;" : "=f"(r.x), "=f"(r.y) : "l"(v)); return r;
}
__device__ __forceinline__ ull ffma2(ull a, ull b, ull c) {
    ull d; asm("fma.rn.f32x2 %0, %1, %2, %3;" : "=l"(d) : "l"(a), "l"(b), "l"(c)); return d;
}
__device__ __forceinline__ ull add2(ull a, ull b) {
    ull d; asm("add.rn.f32x2 %0, %1, %2;" : "=l"(d) : "l"(a), "l"(b)); return d;
}
// accurate fast tanh: 1 - 2/(e^{2x}+1); correct at +-inf of __expf
__device__ __forceinline__ float tanh_fast(float x) {
    float e = __expf(2.0f * x);
    return 1.0f - __fdividef(2.0f, e + 1.0f);
}

// ---- prep kernel: rearrange layer-1 weights into scratch for constant copy ----
extern "C" __global__ void prep_kernel(const float* __restrict__ W1,
                                       const float* __restrict__ b1,
                                       const float* __restrict__ L1,
                                       const float* __restrict__ bl1) {
    int t = blockIdx.x * blockDim.x + threadIdx.x;
    int stride = gridDim.x * blockDim.x;
    for (int idx = t; idx < 500; idx += stride) {
        int j = idx / 5, p = idx % 5;
        d_scratch[CW1T + idx] = pk2(W1[(2 * p) * HID + j], W1[(2 * p + 1) * HID + j]);
        d_scratch[CL1T + idx] = pk2(L1[(2 * p) * HID + j], L1[(2 * p + 1) * HID + j]);
    }
    for (int idx = t; idx < HID; idx += stride) {
        d_scratch[CB1  + idx] = pk2(b1[idx], 0.0f);
        d_scratch[CBL1 + idx] = pk2(bl1[idx], 0.0f);
    }
}

// One fused pass. Layer1: K-pair-packed from constant (WOFF/BOFF), one chain
// per row. Layer2: NP pair-packed weight columns from SMEM (stride ST).
template<int WOFF, int BOFF, int NP, int ST>
__device__ __forceinline__ void layer_pass(
    const ull* __restrict__ w2, const ull* __restrict__ binit,
    const ull* __restrict__ k0, const ull* __restrict__ k1,
    ull* acc_r0, ull* acc_r1)
{
    #pragma unroll
    for (int q = 0; q < NP; q++) { acc_r0[q] = binit[q]; acc_r1[q] = binit[q]; }
    #pragma unroll 2
    for (int j = 0; j < HID; j++) {
        ull a0 = cb[BOFF + j];          // (bias, 0)
        ull a1 = a0;
        #pragma unroll
        for (int p = 0; p < 5; p++) {
            ull w = cb[WOFF + j * 5 + p];   // (w_{2p}, w_{2p+1}) shared by both rows
            a0 = ffma2(k0[p], w, a0);
            a1 = ffma2(k1[p], w, a1);
        }
        float2 u0 = unpk(a0), u1 = unpk(a1);
        float h0s = fmaxf(u0.x + u0.y, 0.0f);
        float h1s = fmaxf(u1.x + u1.y, 0.0f);
        ull h0 = pk2(h0s, h0s);
        ull h1 = pk2(h1s, h1s);
        const ull* w2j = w2 + j * ST;
        #pragma unroll
        for (int q = 0; q < NP / 2; q++) {
            ulonglong2 w = ((const ulonglong2*)w2j)[q];
            acc_r0[2 * q + 0] = ffma2(h0, w.x, acc_r0[2 * q + 0]);
            acc_r0[2 * q + 1] = ffma2(h0, w.y, acc_r0[2 * q + 1]);
            acc_r1[2 * q + 0] = ffma2(h1, w.x, acc_r1[2 * q + 0]);
            acc_r1[2 * q + 1] = ffma2(h1, w.y, acc_r1[2 * q + 1]);
        }
        if (NP & 1) {
            ull w = w2j[NP - 1];
            acc_r0[NP - 1] = ffma2(h0, w, acc_r0[NP - 1]);
            acc_r1[NP - 1] = ffma2(h1, w, acc_r1[NP - 1]);
        }
    }
}

// centroid accs -> row-packed unnormalized softmax weights ewp[M]
template<int M>
__device__ __forceinline__ void centroids_to_ew(
    const ull* cr0, const ull* cr1, float2 av0, float2 av1, ull* ewp)
{
    #pragma unroll
    for (int n = 0; n < M; n++) {
        float2 c0 = unpk(cr0[n]);
        float2 c1 = unpk(cr1[n]);
        float px0 = MAXA_F * tanh_fast(c0.x), py0 = MAXA_F * tanh_fast(c0.y);
        float px1 = MAXA_F * tanh_fast(c1.x), py1 = MAXA_F * tanh_fast(c1.y);
        float dx0 = px0 - av0.x, dy0 = py0 - av0.y;
        float dx1 = px1 - av1.x, dy1 = py1 - av1.y;
        float d0 = sqrtf(fmaf(dx0, dx0, dy0 * dy0));
        float d1 = sqrtf(fmaf(dx1, dx1, dy1 * dy1));
        ewp[n] = pk2(__expf(-BETA_F * d0), __expf(-BETA_F * d1));
    }
}

// fold KP value pairs with 2*KP row-packed ew into num/den (row-packed)
template<int KP>
__device__ __forceinline__ void fold(
    const ull* vr0, const ull* vr1, const ull* ewp, ull& num, ull& den)
{
    #pragma unroll
    for (int k = 0; k < KP; k++) {
        float2 v0 = unpk(vr0[k]);
        float2 v1 = unpk(vr1[k]);
        num = ffma2(ewp[2 * k + 0], pk2(v0.x, v1.x), num);
        num = ffma2(ewp[2 * k + 1], pk2(v0.y, v1.y), num);
        den = add2(den, add2(ewp[2 * k], ewp[2 * k + 1]));
    }
}

extern "C" __global__ void __launch_bounds__(THREADS, 2)
net_kernel(const float* __restrict__ s,  const float* __restrict__ a,
           const float* __restrict__ W2, const float* __restrict__ b2,
           const float* __restrict__ WL2, const float* __restrict__ bL2,
           float* __restrict__ out, int B)
{
    extern __shared__ ull sm[];
    const int t = threadIdx.x;

    // ---- stage layer-2 weights into SMEM ----
    for (int idx = t; idx < HID * 16; idx += THREADS) {   // WL2A: centroids 0..15
        int j = idx / 16, n = idx % 16;
        sm[OFF_WL2A + idx] = pk2(WL2[n * (HID * 2) + 2 * j], WL2[n * (HID * 2) + 2 * j + 1]);
    }
    for (int idx = t; idx < HID * 14; idx += THREADS) {   // WL2B: centroids 16..29
        int j = idx / 14, n = 16 + idx % 14;
        sm[OFF_WL2B + idx] = pk2(WL2[n * (HID * 2) + 2 * j], WL2[n * (HID * 2) + 2 * j + 1]);
    }
    for (int idx = t; idx < HID * 8; idx += THREADS) {    // W2A / W2B pairs
        int j = idx / 8, k = idx % 8;
        sm[OFF_W2A + idx] = pk2(W2[j * NC + 2 * k], W2[j * NC + 2 * k + 1]);
        int kb = 8 + k;
        sm[OFF_W2B + idx] = (kb < 15)
            ? pk2(W2[j * NC + 2 * kb], W2[j * NC + 2 * kb + 1]) : 0ULL;
    }
    if (t < 16) sm[OFF_BL2A + t] = pk2(bL2[2 * t], bL2[2 * t + 1]);
    if (t < 14) { int n = 16 + t; sm[OFF_BL2B + t] = pk2(bL2[2 * n], bL2[2 * n + 1]); }
    if (t < 8) {
        sm[OFF_B2A + t] = pk2(b2[2 * t], b2[2 * t + 1]);
        int kb = 8 + t;
        sm[OFF_B2B + t] = (kb < 15) ? pk2(b2[2 * kb], b2[2 * kb + 1]) : 0ULL;
    }
    __syncthreads();

    const int pairIdx = blockIdx.x * THREADS + t;
    const int r0 = 2 * pairIdx;
    if (r0 >= B) return;
    const bool two = (r0 + 1 < B);
    const int r1 = two ? r0 + 1 : r0;

    // K-pair-packed s per row: k0[p] = (s_r0[2p], s_r0[2p+1])
    ull k0[5], k1[5];
    {
        const ulonglong2* p0 = (const ulonglong2*)(s + (size_t)r0 * SD);  // 16B aligned (r0 even)
        ulonglong2 q0 = p0[0], q1 = p0[1];
        k0[0] = q0.x; k0[1] = q0.y; k0[2] = q1.x; k0[3] = q1.y;
        k0[4] = ((const ull*)(s + (size_t)r0 * SD))[4];
        const ull* p1 = (const ull*)(s + (size_t)r1 * SD);                // 8B aligned
        #pragma unroll
        for (int p = 0; p < 5; p++) k1[p] = p1[p];
    }
    const float2 av0 = *(const float2*)(a + (size_t)r0 * 2);
    const float2 av1 = *(const float2*)(a + (size_t)r1 * 2);

    ull num = 0ULL, den = 0ULL;

    // ===== phase 1: centroids 0..15 =====
    ull ewA[16];
    {
        ull cr0[16], cr1[16];
        layer_pass<CL1T, CBL1, 16, 16>(sm + OFF_WL2A, sm + OFF_BL2A, k0, k1, cr0, cr1);
        centroids_to_ew<16>(cr0, cr1, av0, av1, ewA);
    }
    // ===== phase 2: values 0..15, fold =====
    {
        ull vr0[8], vr1[8];
        layer_pass<CW1T, CB1, 8, 8>(sm + OFF_W2A, sm + OFF_B2A, k0, k1, vr0, vr1);
        fold<8>(vr0, vr1, ewA, num, den);
    }
    // ===== phase 3: centroids 16..29 =====
    ull ewB[14];
    {
        ull cr0[14], cr1[14];
        layer_pass<CL1T, CBL1, 14, 14>(sm + OFF_WL2B, sm + OFF_BL2B, k0, k1, cr0, cr1);
        centroids_to_ew<14>(cr0, cr1, av0, av1, ewB);
    }
    // ===== phase 4: values 16..29, fold =====
    {
        ull vr0[7], vr1[7];
        layer_pass<CW1T, CB1, 7, 8>(sm + OFF_W2B, sm + OFF_B2B, k0, k1, vr0, vr1);
        fold<7>(vr0, vr1, ewB, num, den);
    }

    float2 nn = unpk(num);
    float2 dd = unpk(den);
    out[r0] = nn.x / dd.x;
    if (two) out[r0 + 1] = nn.y / dd.y;
}

extern "C" void kernel_launch(void* const* d_in, const int* in_sizes, int n_in,
                              void* d_out, int out_size) {
    const float* s   = (const float*)d_in[0];
    const float* a   = (const float*)d_in[1];
    const float* W1  = (const float*)d_in[2];
    const float* b1  = (const float*)d_in[3];
    const float* W2  = (const float*)d_in[4];
    const float* b2  = (const float*)d_in[5];
    const float* L1  = (const float*)d_in[6];
    const float* bl1 = (const float*)d_in[7];
    const float* WL2 = (const float*)d_in[8];
    const float* bL2 = (const float*)d_in[9];
    float* out = (float*)d_out;

    const int B = in_sizes[0] / SD;
    const int pairs = (B + 1) / 2;
    const int blocks = (pairs + THREADS - 1) / THREADS;

    // 1) rearrange layer-1 weights into scratch
    prep_kernel<<<4, 256>>>(W1, b1, L1, bl1);
    // 2) scratch -> constant bank (device-to-device, graph-capturable)
    void* scratch_ptr = nullptr;
    cudaGetSymbolAddress(&scratch_ptr, d_scratch);
    cudaMemcpyToSymbolAsync(cb, scratch_ptr, CONST_ULL * sizeof(ull), 0,
                            cudaMemcpyDeviceToDevice, 0);
    // 3) main kernel
    cudaFuncSetAttribute((const void*)net_kernel,
                         cudaFuncAttributeMaxDynamicSharedMemorySize, SMEM_BYTES);
    net_kernel<<<blocks, THREADS, SMEM_BYTES>>>(s, a, W2, b2, WL2, bL2, out, B);
}

// round 5
// speedup vs baseline: 1.2688x; 1.0009x over previous
#include <cuda_runtime.h>

#define THREADS 256
#define HID 100
#define NC 30
#define SD 10
#define BETA_F 3.0f
#define MAXA_F 5.0f

typedef unsigned long long ull;

// ---- constant bank layout (ull units) ----
#define CW1T 0       // [100][5]  (W1[2p][j], W1[2p+1][j])  K-pair-packed, transposed
#define CL1T 500     // [100][5]
#define CB1  1000    // [100]     (b1[j], 0)
#define CBL1 1100    // [100]     (bl1[j], 0)
#define CONST_ULL 1200
__constant__ ull cb[CONST_ULL];
__device__ ull d_scratch[CONST_ULL];

// ---- SMEM layout (ull units, layer-2 only); bases even -> 16B aligned ----
#define OFF_WL2A 0      // [100][16] pairs (x,y), centroids 0..15
#define OFF_WL2B 1600   // [100][14] centroids 16..29
#define OFF_W2A  3000   // [100][8]  value pairs k=0..7
#define OFF_W2B  3800   // [100][8]  value pairs k=8..14 (slot 7 zero)
#define OFF_BL2A 4600   // [16]
#define OFF_BL2B 4616   // [16] (14 used)
#define OFF_B2A  4632   // [8]
#define OFF_B2B  4640   // [8] (7 used)
#define SMEM_ULL 4648
#define SMEM_BYTES (SMEM_ULL * 8)

__device__ __forceinline__ ull pk2(float x, float y) {
    ull r; asm("mov.b64 %0, {%1, %2};" : "=l"(r) : "f"(x), "f"(y)); return r;
}
__device__ __forceinline__ float2 unpk(ull v) {
    float2 r; asm("mov.b64 {%0, %1}, %2;" : "=f"(r.x), "=f"(r.y) : "l"(v)); return r;
}
__device__ __forceinline__ ull ffma2(ull a, ull b, ull c) {
    ull d; asm("fma.rn.f32x2 %0, %1, %2, %3;" : "=l"(d) : "l"(a), "l"(b), "l"(c)); return d;
}
__device__ __forceinline__ ull add2(ull a, ull b) {
    ull d; asm("add.rn.f32x2 %0, %1, %2;" : "=l"(d) : "l"(a), "l"(b)); return d;
}
// accurate fast tanh: 1 - 2/(e^{2x}+1); correct at +-inf of __expf
__device__ __forceinline__ float tanh_fast(float x) {
    float e = __expf(2.0f * x);
    return 1.0f - __fdividef(2.0f, e + 1.0f);
}

// ---- prep kernel: rearrange layer-1 weights into scratch for constant copy ----
extern "C" __global__ void prep_kernel(const float* __restrict__ W1,
                                       const float* __restrict__ b1,
                                       const float* __restrict__ L1,
                                       const float* __restrict__ bl1) {
    int t = blockIdx.x * blockDim.x + threadIdx.x;
    int stride = gridDim.x * blockDim.x;
    for (int idx = t; idx < 500; idx += stride) {
        int j = idx / 5, p = idx % 5;
        d_scratch[CW1T + idx] = pk2(W1[(2 * p) * HID + j], W1[(2 * p + 1) * HID + j]);
        d_scratch[CL1T + idx] = pk2(L1[(2 * p) * HID + j], L1[(2 * p + 1) * HID + j]);
    }
    for (int idx = t; idx < HID; idx += stride) {
        d_scratch[CB1  + idx] = pk2(b1[idx], 0.0f);
        d_scratch[CBL1 + idx] = pk2(bl1[idx], 0.0f);
    }
}

// One fused pass. Layer1: K-pair-packed from constant (WOFF/BOFF), one chain
// per row. Layer2: NP pair-packed weight columns from SMEM (stride ST).
template<int WOFF, int BOFF, int NP, int ST>
__device__ __forceinline__ void layer_pass(
    const ull* __restrict__ w2, const ull* __restrict__ binit,
    const ull* __restrict__ k0, const ull* __restrict__ k1,
    ull* acc_r0, ull* acc_r1)
{
    #pragma unroll
    for (int q = 0; q < NP; q++) { acc_r0[q] = binit[q]; acc_r1[q] = binit[q]; }
    #pragma unroll 2
    for (int j = 0; j < HID; j++) {
        ull a0 = cb[BOFF + j];          // (bias, 0)
        ull a1 = a0;
        #pragma unroll
        for (int p = 0; p < 5; p++) {
            ull w = cb[WOFF + j * 5 + p];   // (w_{2p}, w_{2p+1}) shared by both rows
            a0 = ffma2(k0[p], w, a0);
            a1 = ffma2(k1[p], w, a1);
        }
        float2 u0 = unpk(a0), u1 = unpk(a1);
        float h0s = fmaxf(u0.x + u0.y, 0.0f);
        float h1s = fmaxf(u1.x + u1.y, 0.0f);
        ull h0 = pk2(h0s, h0s);
        ull h1 = pk2(h1s, h1s);
        const ull* w2j = w2 + j * ST;
        #pragma unroll
        for (int q = 0; q < NP / 2; q++) {
            ulonglong2 w = ((const ulonglong2*)w2j)[q];
            acc_r0[2 * q + 0] = ffma2(h0, w.x, acc_r0[2 * q + 0]);
            acc_r0[2 * q + 1] = ffma2(h0, w.y, acc_r0[2 * q + 1]);
            acc_r1[2 * q + 0] = ffma2(h1, w.x, acc_r1[2 * q + 0]);
            acc_r1[2 * q + 1] = ffma2(h1, w.y, acc_r1[2 * q + 1]);
        }
        if (NP & 1) {
            ull w = w2j[NP - 1];
            acc_r0[NP - 1] = ffma2(h0, w, acc_r0[NP - 1]);
            acc_r1[NP - 1] = ffma2(h1, w, acc_r1[NP - 1]);
        }
    }
}

// centroid accs -> row-packed unnormalized softmax weights ewp[M]
template<int M>
__device__ __forceinline__ void centroids_to_ew(
    const ull* cr0, const ull* cr1, float2 av0, float2 av1, ull* ewp)
{
    #pragma unroll
    for (int n = 0; n < M; n++) {
        float2 c0 = unpk(cr0[n]);
        float2 c1 = unpk(cr1[n]);
        float px0 = MAXA_F * tanh_fast(c0.x), py0 = MAXA_F * tanh_fast(c0.y);
        float px1 = MAXA_F * tanh_fast(c1.x), py1 = MAXA_F * tanh_fast(c1.y);
        float dx0 = px0 - av0.x, dy0 = py0 - av0.y;
        float dx1 = px1 - av1.x, dy1 = py1 - av1.y;
        float d0 = sqrtf(fmaf(dx0, dx0, dy0 * dy0));
        float d1 = sqrtf(fmaf(dx1, dx1, dy1 * dy1));
        ewp[n] = pk2(__expf(-BETA_F * d0), __expf(-BETA_F * d1));
    }
}

// fold KP value pairs with 2*KP row-packed ew into num/den (row-packed)
template<int KP>
__device__ __forceinline__ void fold(
    const ull* vr0, const ull* vr1, const ull* ewp, ull& num, ull& den)
{
    #pragma unroll
    for (int k = 0; k < KP; k++) {
        float2 v0 = unpk(vr0[k]);
        float2 v1 = unpk(vr1[k]);
        num = ffma2(ewp[2 * k + 0], pk2(v0.x, v1.x), num);
        num = ffma2(ewp[2 * k + 1], pk2(v0.y, v1.y), num);
        den = add2(den, add2(ewp[2 * k], ewp[2 * k + 1]));
    }
}

extern "C" __global__ void __launch_bounds__(THREADS, 2)
net_kernel(const float* __restrict__ s,  const float* __restrict__ a,
           const float* __restrict__ W2, const float* __restrict__ b2,
           const float* __restrict__ WL2, const float* __restrict__ bL2,
           float* __restrict__ out, int B)
{
    extern __shared__ ull sm[];
    const int t = threadIdx.x;

    // ---- stage layer-2 weights into SMEM ----
    for (int idx = t; idx < HID * 16; idx += THREADS) {   // WL2A: centroids 0..15
        int j = idx / 16, n = idx % 16;
        sm[OFF_WL2A + idx] = pk2(WL2[n * (HID * 2) + 2 * j], WL2[n * (HID * 2) + 2 * j + 1]);
    }
    for (int idx = t; idx < HID * 14; idx += THREADS) {   // WL2B: centroids 16..29
        int j = idx / 14, n = 16 + idx % 14;
        sm[OFF_WL2B + idx] = pk2(WL2[n * (HID * 2) + 2 * j], WL2[n * (HID * 2) + 2 * j + 1]);
    }
    for (int idx = t; idx < HID * 8; idx += THREADS) {    // W2A / W2B pairs
        int j = idx / 8, k = idx % 8;
        sm[OFF_W2A + idx] = pk2(W2[j * NC + 2 * k], W2[j * NC + 2 * k + 1]);
        int kb = 8 + k;
        sm[OFF_W2B + idx] = (kb < 15)
            ? pk2(W2[j * NC + 2 * kb], W2[j * NC + 2 * kb + 1]) : 0ULL;
    }
    if (t < 16) sm[OFF_BL2A + t] = pk2(bL2[2 * t], bL2[2 * t + 1]);
    if (t < 14) { int n = 16 + t; sm[OFF_BL2B + t] = pk2(bL2[2 * n], bL2[2 * n + 1]); }
    if (t < 8) {
        sm[OFF_B2A + t] = pk2(b2[2 * t], b2[2 * t + 1]);
        int kb = 8 + t;
        sm[OFF_B2B + t] = (kb < 15) ? pk2(b2[2 * kb], b2[2 * kb + 1]) : 0ULL;
    }
    __syncthreads();

    const int pairIdx = blockIdx.x * THREADS + t;
    const int r0 = 2 * pairIdx;
    if (r0 >= B) return;
    const bool two = (r0 + 1 < B);
    const int r1 = two ? r0 + 1 : r0;

    // K-pair-packed s per row: k0[p] = (s_r0[2p], s_r0[2p+1])
    ull k0[5], k1[5];
    {
        const ulonglong2* p0 = (const ulonglong2*)(s + (size_t)r0 * SD);  // 16B aligned (r0 even)
        ulonglong2 q0 = p0[0], q1 = p0[1];
        k0[0] = q0.x; k0[1] = q0.y; k0[2] = q1.x; k0[3] = q1.y;
        k0[4] = ((const ull*)(s + (size_t)r0 * SD))[4];
        const ull* p1 = (const ull*)(s + (size_t)r1 * SD);                // 8B aligned
        #pragma unroll
        for (int p = 0; p < 5; p++) k1[p] = p1[p];
    }
    const float2 av0 = *(const float2*)(a + (size_t)r0 * 2);
    const float2 av1 = *(const float2*)(a + (size_t)r1 * 2);

    ull num = 0ULL, den = 0ULL;

    // ===== phase 1: centroids 0..15 =====
    ull ewA[16];
    {
        ull cr0[16], cr1[16];
        layer_pass<CL1T, CBL1, 16, 16>(sm + OFF_WL2A, sm + OFF_BL2A, k0, k1, cr0, cr1);
        centroids_to_ew<16>(cr0, cr1, av0, av1, ewA);
    }
    // ===== phase 2: values 0..15, fold =====
    {
        ull vr0[8], vr1[8];
        layer_pass<CW1T, CB1, 8, 8>(sm + OFF_W2A, sm + OFF_B2A, k0, k1, vr0, vr1);
        fold<8>(vr0, vr1, ewA, num, den);
    }
    // ===== phase 3: centroids 16..29 =====
    ull ewB[14];
    {
        ull cr0[14], cr1[14];
        layer_pass<CL1T, CBL1, 14, 14>(sm + OFF_WL2B, sm + OFF_BL2B, k0, k1, cr0, cr1);
        centroids_to_ew<14>(cr0, cr1, av0, av1, ewB);
    }
    // ===== phase 4: values 16..29, fold =====
    {
        ull vr0[7], vr1[7];
        layer_pass<CW1T, CB1, 7, 8>(sm + OFF_W2B, sm + OFF_B2B, k0, k1, vr0, vr1);
        fold<7>(vr0, vr1, ewB, num, den);
    }

    float2 nn = unpk(num);
    float2 dd = unpk(den);
    out[r0] = nn.x / dd.x;
    if (two) out[r0 + 1] = nn.y / dd.y;
}

extern "C" void kernel_launch(void* const* d_in, const int* in_sizes, int n_in,
                              void* d_out, int out_size) {
    const float* s   = (const float*)d_in[0];
    const float* a   = (const float*)d_in[1];
    const float* W1  = (const float*)d_in[2];
    const float* b1  = (const float*)d_in[3];
    const float* W2  = (const float*)d_in[4];
    const float* b2  = (const float*)d_in[5];
    const float* L1  = (const float*)d_in[6];
    const float* bl1 = (const float*)d_in[7];
    const float* WL2 = (const float*)d_in[8];
    const float* bL2 = (const float*)d_in[9];
    float* out = (float*)d_out;

    const int B = in_sizes[0] / SD;
    const int pairs = (B + 1) / 2;
    const int blocks = (pairs + THREADS - 1) / THREADS;

    // 1) rearrange layer-1 weights into scratch
    prep_kernel<<<4, 256>>>(W1, b1, L1, bl1);
    // 2) scratch -> constant bank (device-to-device, graph-capturable)
    void* scratch_ptr = nullptr;
    cudaGetSymbolAddress(&scratch_ptr, d_scratch);
    cudaMemcpyToSymbolAsync(cb, scratch_ptr, CONST_ULL * sizeof(ull), 0,
                            cudaMemcpyDeviceToDevice, 0);
    // 3) main kernel
    cudaFuncSetAttribute((const void*)net_kernel,
                         cudaFuncAttributeMaxDynamicSharedMemorySize, SMEM_BYTES);
    net_kernel<<<blocks, THREADS, SMEM_BYTES>>>(s, a, W2, b2, WL2, bL2, out, B);
}

// round 7
// speedup vs baseline: 2.0057x; 1.5808x over previous
#include <cuda_runtime.h>
#include <cuda_bf16.h>
#include <cstdint>

#define THREADS 256
#define HID 100
#define NC 30
#define SD 10
#define BETA_F 3.0f
#define MAXA_F 5.0f

typedef unsigned long long ull;

// ---- constant bank (layer-1 weights, K-pair packed) ----
#define CW1T 0       // [100][5] (W1[2p][j], W1[2p+1][j])
#define CL1T 500
#define CB1  1000    // (b1[j], 0)
#define CBL1 1100
#define CONST_ULL 1200
__constant__ ull cb[CONST_ULL];
__device__ ull d_scratch[CONST_ULL];

// ---- B fragments (precomputed in mma fragment-lane order) ----
#define NFRAG_LOC (7 * 8 * 32)   // 7 k-chunks x 8 n-tiles x 32 lanes
#define NFRAG_VAL (7 * 4 * 32)
__device__ uint4 d_bfrag[NFRAG_LOC + NFRAG_VAL];

// ---- SMEM byte layout ----
#define SM_BF   0                         // 2688 * 16 = 43008
#define SM_HT   43008                     // per warp 3072 (hi 1536 + lo 1536), 8 warps
#define SM_EW   67584                     // per warp 32 rows * 40 floats * 4 = 5120
#define SMEM_BYTES 108544

__device__ __forceinline__ ull pk2(float x, float y) {
    ull r; asm("mov.b64 %0, {%1, %2};" : "=l"(r) : "f"(x), "f"(y)); return r;
}
__device__ __forceinline__ float2 unpk(ull v) {
    float2 r; asm("mov.b64 {%0, %1}, %2;" : "=f"(r.x), "=f"(r.y) : "l"(v)); return r;
}
__device__ __forceinline__ ull ffma2(ull a, ull b, ull c) {
    ull d; asm("fma.rn.f32x2 %0, %1, %2, %3;" : "=l"(d) : "l"(a), "l"(b), "l"(c)); return d;
}
__device__ __forceinline__ float tanh_fast(float x) {
    float e = __expf(2.0f * x);
    return 1.0f - __fdividef(2.0f, e + 1.0f);
}
__device__ __forceinline__ uint32_t smem_u32(const void* p) {
    uint32_t a;
    asm("{ .reg .u64 t; cvta.to.shared.u64 t, %1; cvt.u32.u64 %0, t; }" : "=r"(a) : "l"(p));
    return a;
}
__device__ __forceinline__ void mma_bf16(float* c, const uint32_t* A,
                                         uint32_t b0, uint32_t b1) {
    asm volatile(
        "mma.sync.aligned.m16n8k16.row.col.f32.bf16.bf16.f32 "
        "{%0,%1,%2,%3}, {%4,%5,%6,%7}, {%8,%9}, {%0,%1,%2,%3};"
        : "+f"(c[0]), "+f"(c[1]), "+f"(c[2]), "+f"(c[3])
        : "r"(A[0]), "r"(A[1]), "r"(A[2]), "r"(A[3]), "r"(b0), "r"(b1));
}
__device__ __forceinline__ void ldmA(uint32_t* A, uint32_t addr) {
    asm volatile("ldmatrix.sync.aligned.m8n8.x4.shared.b16 {%0,%1,%2,%3}, [%4];"
                 : "=r"(A[0]), "=r"(A[1]), "=r"(A[2]), "=r"(A[3]) : "r"(addr));
}

// ---- prep: layer1 weights -> scratch (for constant); layer2 -> B fragments ----
extern "C" __global__ void prep_kernel(const float* __restrict__ W1,
                                       const float* __restrict__ b1,
                                       const float* __restrict__ W2,
                                       const float* __restrict__ b2,
                                       const float* __restrict__ L1,
                                       const float* __restrict__ bl1,
                                       const float* __restrict__ WL2,
                                       const float* __restrict__ bL2) {
    int t = blockIdx.x * blockDim.x + threadIdx.x;
    int stride = gridDim.x * blockDim.x;
    for (int idx = t; idx < 500; idx += stride) {
        int j = idx / 5, p = idx % 5;
        d_scratch[CW1T + idx] = pk2(W1[(2 * p) * HID + j], W1[(2 * p + 1) * HID + j]);
        d_scratch[CL1T + idx] = pk2(L1[(2 * p) * HID + j], L1[(2 * p + 1) * HID + j]);
    }
    for (int idx = t; idx < HID; idx += stride) {
        d_scratch[CB1  + idx] = pk2(b1[idx], 0.0f);
        d_scratch[CBL1 + idx] = pk2(bl1[idx], 0.0f);
    }
    for (int idx = t; idx < NFRAG_LOC + NFRAG_VAL; idx += stride) {
        bool isloc = idx < NFRAG_LOC;
        int rel = isloc ? idx : idx - NFRAG_LOC;
        int lane = rel & 31;
        int f = rel >> 5;
        int nt = isloc ? 8 : 4;
        int q = f / nt, tn = f % nt;
        int k0 = q * 16 + 2 * (lane & 3);
        int n  = tn * 8 + (lane >> 2);
        float v[4];
        #pragma unroll
        for (int e = 0; e < 4; e++) {
            int k = k0 + (e >> 1) * 8 + (e & 1);
            float x = 0.0f;
            if (isloc) {
                if (n < 60) {
                    if (k < HID)       x = WL2[(n >> 1) * 200 + k * 2 + (n & 1)];
                    else if (k == HID) x = bL2[n];
                }
            } else {
                if (n < NC) {
                    if (k < HID)       x = W2[k * NC + n];
                    else if (k == HID) x = b2[n];
                }
            }
            v[e] = x;
        }
        unsigned short hb[4], lb[4];
        #pragma unroll
        for (int e = 0; e < 4; e++) {
            __nv_bfloat16 h = __float2bfloat16(v[e]);
            hb[e] = __bfloat16_as_ushort(h);
            lb[e] = __bfloat16_as_ushort(__float2bfloat16(v[e] - __bfloat162float(h)));
        }
        uint4 o;
        o.x = (uint32_t)hb[0] | ((uint32_t)hb[1] << 16);
        o.y = (uint32_t)hb[2] | ((uint32_t)hb[3] << 16);
        o.z = (uint32_t)lb[0] | ((uint32_t)lb[1] << 16);
        o.w = (uint32_t)lb[2] | ((uint32_t)lb[3] << 16);
        d_bfrag[idx] = o;
    }
}

// layer1 for a 16-unit chunk: fp32 from constant, split to bf16 hi/lo pairs
template<int WOFF, int BOFF>
__device__ __forceinline__ void l1_chunk(int q, const ull* kk,
                                         uint32_t* hv, uint32_t* lv) {
    #pragma unroll
    for (int p = 0; p < 8; p++) {
        const int j0 = q * 16 + 2 * p;
        const int j1 = j0 + 1;
        float h0 = 0.0f, h1 = 0.0f;
        if (j0 < HID) {
            ull acc = cb[BOFF + j0];
            #pragma unroll
            for (int pp = 0; pp < 5; pp++)
                acc = ffma2(kk[pp], cb[WOFF + j0 * 5 + pp], acc);
            float2 u = unpk(acc);
            h0 = fmaxf(u.x + u.y, 0.0f);
        } else if (j0 == HID) h0 = 1.0f;       // bias-fold "ones" column
        if (j1 < HID) {
            ull acc = cb[BOFF + j1];
            #pragma unroll
            for (int pp = 0; pp < 5; pp++)
                acc = ffma2(kk[pp], cb[WOFF + j1 * 5 + pp], acc);
            float2 u = unpk(acc);
            h1 = fmaxf(u.x + u.y, 0.0f);
        } else if (j1 == HID) h1 = 1.0f;
        uint32_t hi;
        asm("cvt.rn.bf16x2.f32 %0, %1, %2;" : "=r"(hi) : "f"(h1), "f"(h0));
        float l0 = h0 - __uint_as_float(hi << 16);
        float l1 = h1 - __uint_as_float(hi & 0xFFFF0000u);
        uint32_t lo;
        asm("cvt.rn.bf16x2.f32 %0, %1, %2;" : "=r"(lo) : "f"(l1), "f"(l0));
        hv[p] = hi; lv[p] = lo;
    }
}

// fused layer1 + split-bf16 mma GEMM for one branch (32 rows/warp, N = NT*8)
template<int WOFF, int BOFF, int NT>
__device__ __forceinline__ void gemm_branch(
    const uint4* __restrict__ bfrag, const ull* kk,
    char* ht_hi, char* ht_lo, uint32_t ht_hi_u, uint32_t ht_lo_u,
    uint32_t lmoff, int lane, float (&c)[2][NT][4])
{
    #pragma unroll
    for (int m = 0; m < 2; m++)
        #pragma unroll
        for (int tn = 0; tn < NT; tn++)
            #pragma unroll
            for (int e = 0; e < 4; e++) c[m][tn][e] = 0.0f;

    for (int q = 0; q < 7; q++) {
        uint32_t hv[8], lv[8];
        l1_chunk<WOFF, BOFF>(q, kk, hv, lv);
        __syncwarp();
        *(uint4*)(ht_hi + lane * 48)      = make_uint4(hv[0], hv[1], hv[2], hv[3]);
        *(uint4*)(ht_hi + lane * 48 + 16) = make_uint4(hv[4], hv[5], hv[6], hv[7]);
        *(uint4*)(ht_lo + lane * 48)      = make_uint4(lv[0], lv[1], lv[2], lv[3]);
        *(uint4*)(ht_lo + lane * 48 + 16) = make_uint4(lv[4], lv[5], lv[6], lv[7]);
        __syncwarp();
        uint32_t Ah0[4], Ah1[4], Al0[4], Al1[4];
        ldmA(Ah0, ht_hi_u + lmoff);
        ldmA(Ah1, ht_hi_u + 768 + lmoff);   // Mtile1 = rows 16..31
        ldmA(Al0, ht_lo_u + lmoff);
        ldmA(Al1, ht_lo_u + 768 + lmoff);
        const uint4* bq = bfrag + q * NT * 32 + lane;
        #pragma unroll
        for (int tn = 0; tn < NT; tn++) {
            uint4 b = bq[tn * 32];
            mma_bf16(c[0][tn], Ah0, b.x, b.y);   // hi*hi
            mma_bf16(c[0][tn], Ah0, b.z, b.w);   // hi*lo
            mma_bf16(c[0][tn], Al0, b.x, b.y);   // lo*hi
            mma_bf16(c[1][tn], Ah1, b.x, b.y);
            mma_bf16(c[1][tn], Ah1, b.z, b.w);
            mma_bf16(c[1][tn], Al1, b.x, b.y);
        }
    }
}

extern "C" __global__ void __launch_bounds__(THREADS, 2)
net_kernel(const float* __restrict__ s, const float* __restrict__ a,
           float* __restrict__ out, int B)
{
    extern __shared__ __align__(16) char smem[];
    const int t = threadIdx.x;
    const int lane = t & 31;
    const int warp = t >> 5;
    const int lq = lane & 3, lr = lane >> 2;

    // stage B fragments into SMEM
    uint4* bf = (uint4*)(smem + SM_BF);
    for (int i = t; i < NFRAG_LOC + NFRAG_VAL; i += THREADS) bf[i] = d_bfrag[i];
    __syncthreads();

    char* ht_hi = smem + SM_HT + warp * 3072;
    char* ht_lo = ht_hi + 1536;
    float* ewp = (float*)(smem + SM_EW + warp * 5120);
    const uint32_t ht_hi_u = smem_u32(ht_hi);
    const uint32_t ht_lo_u = smem_u32(ht_lo);
    const uint32_t lmoff = (uint32_t)((lane & 15) * 48 + ((lane >> 4) << 4));

    const int base = blockIdx.x * 256 + warp * 32;
    const int myrow = base + lane;
    const int rc = myrow < B ? myrow : B - 1;

    ull kk[5];
    {
        const ull* sp = (const ull*)(s + (size_t)rc * SD);
        #pragma unroll
        for (int p = 0; p < 5; p++) kk[p] = sp[p];
    }

    // ---- loc branch GEMM (N=64: 30 centroid (x,y) pairs + padding) ----
    float cl[2][8][4];
    gemm_branch<CL1T, CBL1, 8>(bf, kk, ht_hi, ht_lo, ht_hi_u, ht_lo_u, lmoff, lane, cl);

    // action vectors for my 4 epilogue rows
    float2 av[2][2];
    #pragma unroll
    for (int m = 0; m < 2; m++)
        #pragma unroll
        for (int h = 0; h < 2; h++) {
            int r = base + m * 16 + lr + h * 8;
            r = r < B ? r : B - 1;
            av[m][h] = *(const float2*)(a + (size_t)r * 2);
        }

    // ---- loc epilogue: centroids -> ew (SMEM relay) + den partials ----
    float den[4] = {0.0f, 0.0f, 0.0f, 0.0f};
    #pragma unroll
    for (int m = 0; m < 2; m++) {
        #pragma unroll
        for (int tn = 0; tn < 8; tn++) {
            int n = tn * 4 + lq;
            float e0 = 0.0f, e1 = 0.0f;
            if (n < NC) {
                float px = MAXA_F * tanh_fast(cl[m][tn][0]);
                float py = MAXA_F * tanh_fast(cl[m][tn][1]);
                float dx = px - av[m][0].x, dy = py - av[m][0].y;
                e0 = __expf(-BETA_F * sqrtf(fmaf(dx, dx, dy * dy)));
                px = MAXA_F * tanh_fast(cl[m][tn][2]);
                py = MAXA_F * tanh_fast(cl[m][tn][3]);
                dx = px - av[m][1].x; dy = py - av[m][1].y;
                e1 = __expf(-BETA_F * sqrtf(fmaf(dx, dx, dy * dy)));
            }
            ewp[(m * 16 + lr) * 40 + n]     = e0;
            ewp[(m * 16 + lr + 8) * 40 + n] = e1;
            den[m * 2 + 0] += e0;
            den[m * 2 + 1] += e1;
        }
    }
    #pragma unroll
    for (int i = 0; i < 4; i++) {
        den[i] += __shfl_xor_sync(0xFFFFFFFFu, den[i], 1);
        den[i] += __shfl_xor_sync(0xFFFFFFFFu, den[i], 2);
    }
    __syncwarp();

    // ---- val branch GEMM (N=32: 30 values + padding) ----
    float cv[2][4][4];
    gemm_branch<CW1T, CB1, 4>(bf + NFRAG_LOC, kk, ht_hi, ht_lo, ht_hi_u, ht_lo_u,
                              lmoff, lane, cv);

    // ---- val epilogue: num = sum ew*v (ew via SMEM, padded n have ew=0) ----
    float num[4] = {0.0f, 0.0f, 0.0f, 0.0f};
    #pragma unroll
    for (int m = 0; m < 2; m++) {
        #pragma unroll
        for (int tv = 0; tv < 4; tv++) {
            int n0 = tv * 8 + 2 * lq;
            float2 e0 = *(float2*)(ewp + (m * 16 + lr) * 40 + n0);
            float2 e1 = *(float2*)(ewp + (m * 16 + lr + 8) * 40 + n0);
            num[m * 2 + 0] += cv[m][tv][0] * e0.x + cv[m][tv][1] * e0.y;
            num[m * 2 + 1] += cv[m][tv][2] * e1.x + cv[m][tv][3] * e1.y;
        }
    }
    #pragma unroll
    for (int i = 0; i < 4; i++) {
        num[i] += __shfl_xor_sync(0xFFFFFFFFu, num[i], 1);
        num[i] += __shfl_xor_sync(0xFFFFFFFFu, num[i], 2);
    }
    if (lq == 0) {
        #pragma unroll
        for (int m = 0; m < 2; m++)
            #pragma unroll
            for (int h = 0; h < 2; h++) {
                int r = base + m * 16 + lr + h * 8;
                if (r < B) out[r] = num[m * 2 + h] / den[m * 2 + h];
            }
    }
}

extern "C" void kernel_launch(void* const* d_in, const int* in_sizes, int n_in,
                              void* d_out, int out_size) {
    const float* s   = (const float*)d_in[0];
    const float* a   = (const float*)d_in[1];
    const float* W1  = (const float*)d_in[2];
    const float* b1  = (const float*)d_in[3];
    const float* W2  = (const float*)d_in[4];
    const float* b2  = (const float*)d_in[5];
    const float* L1  = (const float*)d_in[6];
    const float* bl1 = (const float*)d_in[7];
    const float* WL2 = (const float*)d_in[8];
    const float* bL2 = (const float*)d_in[9];
    float* out = (float*)d_out;

    const int B = in_sizes[0] / SD;
    const int blocks = (B + 255) / 256;

    prep_kernel<<<8, 256>>>(W1, b1, W2, b2, L1, bl1, WL2, bL2);
    void* scratch_ptr = nullptr;
    cudaGetSymbolAddress(&scratch_ptr, d_scratch);
    cudaMemcpyToSymbolAsync(cb, scratch_ptr, CONST_ULL * sizeof(ull), 0,
                            cudaMemcpyDeviceToDevice, 0);

    cudaFuncSetAttribute((const void*)net_kernel,
                         cudaFuncAttributeMaxDynamicSharedMemorySize, SMEM_BYTES);
    net_kernel<<<blocks, THREADS, SMEM_BYTES>>>(s, a, out, B);
}